// round 15
// baseline (speedup 1.0000x reference)
#include <cuda_runtime.h>
#include <cuda_bf16.h>
#include <math.h>
#include <stdint.h>

// Problem constants
#define BB 64
#define HH 1024
#define SS_ 1024
#define VV 32000
#define KIH 2048   // E + H
#define G3H 3072   // 3*H
#define NTILES 250 // logits tiles of 128 cols

// ---------------- scratch (static device globals) ----------------
__device__ __nv_bfloat16 g_x0hi[BB * KIH];
__device__ __nv_bfloat16 g_x0lo[BB * KIH];
__device__ __nv_bfloat16 g_hhi [BB * HH];
__device__ __nv_bfloat16 g_hlo [BB * HH];
__device__ __nv_bfloat16 g_zhi [BB * KIH];   // [b][ h | ctx ]
__device__ float g_gi[BB * G3H];             // [b][n]
__device__ float g_gh[BB * G3H];             // [b][n]
__device__ float g_z [BB * KIH];             // fp32 h (attn uses [0,1024))
__device__ float g_energy[BB * SS_];
__device__ float g_pm[BB * 8];
__device__ float g_pl[BB * 8];
__device__ float g_pacc[BB * 8 * HH];
__device__ float g_logits[BB * VV];          // biased logits
__device__ float g_tm[NTILES * BB];          // per-tile row max
__device__ float g_tl[NTILES * BB];          // per-tile row sumexp
__device__ float g_lse[BB];

// ---------------- helpers ----------------
__device__ __forceinline__ uint32_t smem_u32(const void* p) {
    uint32_t a;
    asm("{ .reg .u64 t; cvta.to.shared.u64 t, %1; cvt.u32.u64 %0, t; }" : "=r"(a) : "l"(p));
    return a;
}
__device__ __forceinline__ void ldm_x4(uint32_t& r0, uint32_t& r1, uint32_t& r2, uint32_t& r3,
                                       uint32_t addr) {
    asm volatile("ldmatrix.sync.aligned.m8n8.x4.shared.b16 {%0,%1,%2,%3}, [%4];"
        : "=r"(r0), "=r"(r1), "=r"(r2), "=r"(r3) : "r"(addr));
}
__device__ __forceinline__ void mma_bf16(float* c, const uint32_t* a, const uint32_t* b) {
    asm volatile("mma.sync.aligned.m16n8k16.row.col.f32.bf16.bf16.f32 "
        "{%0,%1,%2,%3}, {%4,%5,%6,%7}, {%8,%9}, {%0,%1,%2,%3};"
        : "+f"(c[0]), "+f"(c[1]), "+f"(c[2]), "+f"(c[3])
        : "r"(a[0]), "r"(a[1]), "r"(a[2]), "r"(a[3]), "r"(b[0]), "r"(b[1]));
}
__device__ __forceinline__ uint2 cvt_hi_pair(float4 x) {
    __nv_bfloat162 h0 = __floats2bfloat162_rn(x.x, x.y);
    __nv_bfloat162 h1 = __floats2bfloat162_rn(x.z, x.w);
    uint2 r; r.x = *(uint32_t*)&h0; r.y = *(uint32_t*)&h1;
    return r;
}

__device__ __forceinline__ float warpRedSum(float v) {
    #pragma unroll
    for (int o = 16; o; o >>= 1) v += __shfl_xor_sync(0xffffffffu, v, o);
    return v;
}
__device__ __forceinline__ float warpRedMax(float v) {
    #pragma unroll
    for (int o = 16; o; o >>= 1) v = fmaxf(v, __shfl_xor_sync(0xffffffffu, v, o));
    return v;
}

// ================= gates GEMM (3-product split bf16, unchanged) =================
#define PITCH  72                      // bf16 elements per smem row (144 B)
#define ABYTES (128 * PITCH * 2)       // 18432: 64 hi rows + 64 lo rows
#define WOFF   ABYTES
#define BUFSZ  (2 * ABYTES)            // 36864 per buffer (A + W)
#define SMEM_GEMM (2 * BUFSZ)          // 73728 double-buffered

__device__ __forceinline__ void mma_gemm3(
    const float* __restrict__ W, int K,
    const __nv_bfloat16* __restrict__ Ahi, const __nv_bfloat16* __restrict__ Alo,
    float* __restrict__ OUT, int ldout, int n0)
{
    extern __shared__ char smem[];
    const uint32_t sbase = smem_u32(smem);
    const int tid = threadIdx.x;
    const int w = tid >> 5, l = tid & 31;
    const int wm = w >> 2;
    const int wn = w & 3;
    const int nch = K >> 6;

    const int ar   = tid >> 1;
    const int aseg = (tid & 1) * 32;
    const __nv_bfloat16* asrc =
        (ar < 64 ? Ahi + (long)ar * K : Alo + (long)(ar - 64) * K) + aseg;
    const int adst = (ar * PITCH + aseg) * 2;

    const int wr   = tid >> 2;
    const int wseg = (tid & 3) * 16;
    const float* wsrc = W + (long)(n0 + wr) * K + wseg;
    const int wdst_hi = (wr * PITCH + wseg) * 2;
    const int wdst_lo = ((wr + 64) * PITCH + wseg) * 2;

    float acc[2][2][4];
    #pragma unroll
    for (int i = 0; i < 2; ++i)
        #pragma unroll
        for (int j = 0; j < 2; ++j)
            #pragma unroll
            for (int q = 0; q < 4; ++q) acc[i][j][q] = 0.f;

    uint4  stA[4];
    float4 stW[4];

    #pragma unroll
    for (int i = 0; i < 4; ++i) stA[i] = *(const uint4*)(asrc + i * 8);
    #pragma unroll
    for (int i = 0; i < 4; ++i) stW[i] = *(const float4*)(wsrc + i * 4);
    {
        char* bufA = smem;
        char* bufW = smem + WOFF;
        #pragma unroll
        for (int i = 0; i < 4; ++i) *(uint4*)(bufA + adst + i * 16) = stA[i];
        #pragma unroll
        for (int i = 0; i < 4; ++i) {
            float4 x = stW[i];
            uint2 hp = cvt_hi_pair(x);
            __nv_bfloat162 h0 = *(__nv_bfloat162*)&hp.x;
            __nv_bfloat162 h1 = *(__nv_bfloat162*)&hp.y;
            __nv_bfloat162 l0 = __floats2bfloat162_rn(x.x - __bfloat162float(h0.x),
                                                      x.y - __bfloat162float(h0.y));
            __nv_bfloat162 l1 = __floats2bfloat162_rn(x.z - __bfloat162float(h1.x),
                                                      x.w - __bfloat162float(h1.y));
            uint2 lp; lp.x = *(uint32_t*)&l0; lp.y = *(uint32_t*)&l1;
            *(uint2*)(bufW + wdst_hi + i * 8) = hp;
            *(uint2*)(bufW + wdst_lo + i * 8) = lp;
        }
    }
    __syncthreads();

    for (int c = 0; c < nch; ++c) {
        const int cur = c & 1;
        if (c + 1 < nch) {
            const __nv_bfloat16* as = asrc + (c + 1) * 64;
            #pragma unroll
            for (int i = 0; i < 4; ++i) stA[i] = *(const uint4*)(as + i * 8);
            const float* ws = wsrc + (c + 1) * 64;
            #pragma unroll
            for (int i = 0; i < 4; ++i) stW[i] = *(const float4*)(ws + i * 4);
        }
        const uint32_t sA = sbase + cur * BUFSZ;
        const uint32_t sW = sA + WOFF;

        #pragma unroll
        for (int ks = 0; ks < 4; ++ks) {
            const int k = ks * 16;
            uint32_t ah[2][4], al[2][4], bh[4], bl[4];
            const int rowa = l & 15;
            const int cola = k + (l >> 4) * 8;
            #pragma unroll
            for (int mt = 0; mt < 2; ++mt) {
                const int rhi = wm * 32 + mt * 16 + rowa;
                ldm_x4(ah[mt][0], ah[mt][1], ah[mt][2], ah[mt][3],
                       sA + (rhi * PITCH + cola) * 2);
                ldm_x4(al[mt][0], al[mt][1], al[mt][2], al[mt][3],
                       sA + ((rhi + 64) * PITCH + cola) * 2);
            }
            const int rowb = wn * 16 + ((l >> 4) << 3) + (l & 7);
            const int colb = k + ((l >> 3) & 1) * 8;
            ldm_x4(bh[0], bh[1], bh[2], bh[3], sW + (rowb * PITCH + colb) * 2);
            ldm_x4(bl[0], bl[1], bl[2], bl[3], sW + ((rowb + 64) * PITCH + colb) * 2);

            #pragma unroll
            for (int mt = 0; mt < 2; ++mt)
                #pragma unroll
                for (int nt = 0; nt < 2; ++nt) {
                    mma_bf16(acc[mt][nt], ah[mt], &bh[nt * 2]);
                    mma_bf16(acc[mt][nt], ah[mt], &bl[nt * 2]);
                    mma_bf16(acc[mt][nt], al[mt], &bh[nt * 2]);
                }
        }

        if (c + 1 < nch) {
            char* bufA = smem + (cur ^ 1) * BUFSZ;
            char* bufW = bufA + WOFF;
            #pragma unroll
            for (int i = 0; i < 4; ++i) *(uint4*)(bufA + adst + i * 16) = stA[i];
            #pragma unroll
            for (int i = 0; i < 4; ++i) {
                float4 x = stW[i];
                uint2 hp = cvt_hi_pair(x);
                __nv_bfloat162 h0 = *(__nv_bfloat162*)&hp.x;
                __nv_bfloat162 h1 = *(__nv_bfloat162*)&hp.y;
                __nv_bfloat162 l0 = __floats2bfloat162_rn(x.x - __bfloat162float(h0.x),
                                                          x.y - __bfloat162float(h0.y));
                __nv_bfloat162 l1 = __floats2bfloat162_rn(x.z - __bfloat162float(h1.x),
                                                          x.w - __bfloat162float(h1.y));
                uint2 lp; lp.x = *(uint32_t*)&l0; lp.y = *(uint32_t*)&l1;
                *(uint2*)(bufW + wdst_hi + i * 8) = hp;
                *(uint2*)(bufW + wdst_lo + i * 8) = lp;
            }
        }
        __syncthreads();
    }

    #pragma unroll
    for (int mt = 0; mt < 2; ++mt) {
        #pragma unroll
        for (int nt = 0; nt < 2; ++nt) {
            const int row = wm * 32 + mt * 16 + (l >> 2);
            const int col = n0 + wn * 16 + nt * 8 + (l & 3) * 2;
            *(float2*)(OUT + (long)row * ldout + col)       = make_float2(acc[mt][nt][0], acc[mt][nt][1]);
            *(float2*)(OUT + (long)(row + 8) * ldout + col) = make_float2(acc[mt][nt][2], acc[mt][nt][3]);
        }
    }
}

__global__ void __launch_bounds__(256, 2) gates_mma_kernel(
    const float* __restrict__ wih, const float* __restrict__ whh)
{
    if (blockIdx.x < 48)
        mma_gemm3(wih, KIH, g_x0hi, g_x0lo, g_gi, G3H, blockIdx.x * 64);
    else
        mma_gemm3(whh, HH, g_hhi, g_hlo, g_gh, G3H, (blockIdx.x - 48) * 64);
}

// ================= logits GEMM: disjoint W coverage, depth-4 W pipe, 128-k A chunks =================
// A smem: 64 rows x 136 bf16 pitch (272 B rows; conflict-free for ldmatrix), double buffered
#define LPITCH   136
#define LA_BYTES (64 * LPITCH * 2)    // 17408 per buffer
#define SMEM_LOG (2 * LA_BYTES)       // 34816

__global__ void __launch_bounds__(256, 2) logits_mma_kernel(const float* __restrict__ outW,
                                                            const float* __restrict__ outb)
{
    extern __shared__ char smem[];
    const uint32_t sbase = smem_u32(smem);
    const int tid = threadIdx.x;
    const int w = tid >> 5, l = tid & 31;
    const int tile = blockIdx.x;
    const int n0 = tile * 128;

    // A staging: row = tid>>2 (0..63), 32 bf16 per thread per 128-k chunk
    const int ar   = tid >> 2;
    const int aseg = (tid & 3) * 32;
    const __nv_bfloat16* asrc = g_zhi + (long)ar * KIH + aseg;
    const int adst = (ar * LPITCH + aseg) * 2;

    // W direct pointers: warp w covers n-rows [n0+16w, n0+16w+16) -- disjoint across warps
    const float* wp0 = outW + (long)(n0 + w * 16 + 0 + (l >> 2)) * KIH + (l & 3) * 2;
    const float* wp1 = outW + (long)(n0 + w * 16 + 8 + (l >> 2)) * KIH + (l & 3) * 2;

    float acc[4][2][4];
    #pragma unroll
    for (int i = 0; i < 4; ++i)
        #pragma unroll
        for (int j = 0; j < 2; ++j)
            #pragma unroll
            for (int q = 0; q < 4; ++q) acc[i][j][q] = 0.f;

    // prologue: stage A chunk 0; load W steps 0..3 (depth-4 register pipeline)
    {
        char* buf = smem;
        *(uint4*)(buf + adst)      = *(const uint4*)(asrc);
        *(uint4*)(buf + adst + 16) = *(const uint4*)(asrc + 8);
        *(uint4*)(buf + adst + 32) = *(const uint4*)(asrc + 16);
        *(uint4*)(buf + adst + 48) = *(const uint4*)(asrc + 24);
    }
    float2 wf[4][4];
    #pragma unroll
    for (int s = 0; s < 4; ++s) {
        const int kn = s * 16;
        wf[s][0] = *(const float2*)(wp0 + kn);  wf[s][1] = *(const float2*)(wp0 + kn + 8);
        wf[s][2] = *(const float2*)(wp1 + kn);  wf[s][3] = *(const float2*)(wp1 + kn + 8);
    }
    __syncthreads();

    for (int c = 0; c < 16; ++c) {          // 16 chunks of 128 k
        const uint32_t sA = sbase + (c & 1) * LA_BYTES;
        uint4 an0, an1, an2, an3;
        if (c + 1 < 16) {
            const __nv_bfloat16* as = asrc + (c + 1) * 128;
            an0 = *(const uint4*)(as);
            an1 = *(const uint4*)(as + 8);
            an2 = *(const uint4*)(as + 16);
            an3 = *(const uint4*)(as + 24);
        }
        #pragma unroll
        for (int ks = 0; ks < 8; ++ks) {    // 8 k16-steps per chunk
            const int kk = c * 8 + ks;
            const int slot = kk & 3;
            // convert current W step to bf16 fragments
            uint32_t breg[4];
            #pragma unroll
            for (int i = 0; i < 4; ++i) {
                __nv_bfloat162 bb = __floats2bfloat162_rn(wf[slot][i].x, wf[slot][i].y);
                breg[i] = *(uint32_t*)&bb;
            }
            // refill this slot with step kk+4 (pipeline depth 4)
            if (kk + 4 < 128) {
                const int kn = (kk + 4) * 16;
                wf[slot][0] = *(const float2*)(wp0 + kn);  wf[slot][1] = *(const float2*)(wp0 + kn + 8);
                wf[slot][2] = *(const float2*)(wp1 + kn);  wf[slot][3] = *(const float2*)(wp1 + kn + 8);
            }
            // A frags from smem: all 4 m-tiles
            const int rowa = l & 15;
            const int cola = ks * 16 + (l >> 4) * 8;
            uint32_t ah[4][4];
            #pragma unroll
            for (int mt = 0; mt < 4; ++mt) {
                ldm_x4(ah[mt][0], ah[mt][1], ah[mt][2], ah[mt][3],
                       sA + ((mt * 16 + rowa) * LPITCH + cola) * 2);
            }
            // 8 MMAs
            #pragma unroll
            for (int mt = 0; mt < 4; ++mt) {
                mma_bf16(acc[mt][0], ah[mt], &breg[0]);
                mma_bf16(acc[mt][1], ah[mt], &breg[2]);
            }
        }
        if (c + 1 < 16) {
            char* buf = smem + ((c + 1) & 1) * LA_BYTES;
            *(uint4*)(buf + adst)      = an0;
            *(uint4*)(buf + adst + 16) = an1;
            *(uint4*)(buf + adst + 32) = an2;
            *(uint4*)(buf + adst + 48) = an3;
        }
        __syncthreads();
    }

    // bias add
    #pragma unroll
    for (int nt = 0; nt < 2; ++nt) {
        const int col = n0 + w * 16 + nt * 8 + (l & 3) * 2;
        float2 bb = *(const float2*)(outb + col);
        #pragma unroll
        for (int mt = 0; mt < 4; ++mt) {
            acc[mt][nt][0] += bb.x; acc[mt][nt][1] += bb.y;
            acc[mt][nt][2] += bb.x; acc[mt][nt][3] += bb.y;
        }
    }

    // store biased logits
    #pragma unroll
    for (int mt = 0; mt < 4; ++mt) {
        #pragma unroll
        for (int nt = 0; nt < 2; ++nt) {
            const int row = mt * 16 + (l >> 2);
            const int col = n0 + w * 16 + nt * 8 + (l & 3) * 2;
            *(float2*)(g_logits + (long)row * VV + col)       = make_float2(acc[mt][nt][0], acc[mt][nt][1]);
            *(float2*)(g_logits + (long)(row + 8) * VV + col) = make_float2(acc[mt][nt][2], acc[mt][nt][3]);
        }
    }

    // per-row tile stats (max + sumexp over 128 cols; 8 warp-columns of 16)
    {
        float* sm_em = (float*)smem;         // [8][64]
        float* sm_el = sm_em + 512;          // [8][64]
        float rmax[8], rsum[8];
        #pragma unroll
        for (int r = 0; r < 8; ++r) {
            const int mt = r >> 1, hf = r & 1;
            float v = fmaxf(fmaxf(acc[mt][0][hf * 2], acc[mt][0][hf * 2 + 1]),
                            fmaxf(acc[mt][1][hf * 2], acc[mt][1][hf * 2 + 1]));
            v = fmaxf(v, __shfl_xor_sync(0xffffffffu, v, 1));
            v = fmaxf(v, __shfl_xor_sync(0xffffffffu, v, 2));
            rmax[r] = v;
        }
        __syncthreads();
        if ((l & 3) == 0) {
            #pragma unroll
            for (int r = 0; r < 8; ++r) {
                const int mt = r >> 1, hf = r & 1;
                const int row = mt * 16 + hf * 8 + (l >> 2);
                sm_em[w * 64 + row] = rmax[r];
            }
        }
        __syncthreads();
        #pragma unroll
        for (int r = 0; r < 8; ++r) {
            const int mt = r >> 1, hf = r & 1;
            const int row = mt * 16 + hf * 8 + (l >> 2);
            float gm = -INFINITY;
            #pragma unroll
            for (int j = 0; j < 8; ++j) gm = fmaxf(gm, sm_em[j * 64 + row]);
            rmax[r] = gm;
            float s = __expf(acc[mt][0][hf * 2]     - gm) + __expf(acc[mt][0][hf * 2 + 1] - gm)
                    + __expf(acc[mt][1][hf * 2]     - gm) + __expf(acc[mt][1][hf * 2 + 1] - gm);
            s += __shfl_xor_sync(0xffffffffu, s, 1);
            s += __shfl_xor_sync(0xffffffffu, s, 2);
            rsum[r] = s;
        }
        __syncthreads();
        if ((l & 3) == 0) {
            #pragma unroll
            for (int r = 0; r < 8; ++r) {
                const int mt = r >> 1, hf = r & 1;
                const int row = mt * 16 + hf * 8 + (l >> 2);
                sm_el[w * 64 + row] = rsum[r];
            }
        }
        __syncthreads();
        if (w == 0 && (l & 3) == 0) {
            #pragma unroll
            for (int r = 0; r < 8; ++r) {
                const int mt = r >> 1, hf = r & 1;
                const int row = mt * 16 + hf * 8 + (l >> 2);
                float tot = 0.f;
                #pragma unroll
                for (int j = 0; j < 8; ++j) tot += sm_el[j * 64 + row];
                g_tm[tile * BB + row] = rmax[r];
                g_tl[tile * BB + row] = tot;
            }
        }
    }
}

// ---------------- kernels ----------------

// split x0 = [emb|lctx] and hprev into bf16 hi/lo
__global__ void prep_kernel(const int* __restrict__ wi,
                            const float* __restrict__ lctx,
                            const float* __restrict__ emb,
                            const float* __restrict__ lhid)
{
    int t = blockIdx.x * blockDim.x + threadIdx.x;   // 196608
    if (t < BB * KIH) {
        int b = t >> 11, k = t & 2047;
        float x = (k < 1024) ? emb[(long)wi[b] * 1024 + k] : lctx[(long)b * HH + (k - 1024)];
        __nv_bfloat16 h = __float2bfloat16(x);
        g_x0hi[t] = h;
        g_x0lo[t] = __float2bfloat16(x - __bfloat162float(h));
    } else {
        int t2 = t - BB * KIH;
        float x = lhid[t2];
        __nv_bfloat16 h = __float2bfloat16(x);
        g_hhi[t2] = h;
        g_hlo[t2] = __float2bfloat16(x - __bfloat162float(h));
    }
}

// GRU gate nonlinearity -> h (fp32 + bf16 hi for logits A)
__global__ void gru_kernel(const float* __restrict__ bih,
                           const float* __restrict__ bhh,
                           const float* __restrict__ hprev,
                           float* __restrict__ out_hidden)
{
    int t = blockIdx.x * blockDim.x + threadIdx.x;   // 65536
    int b = t >> 10;
    int j = t & 1023;
    const float* gi = g_gi + (long)b * G3H;
    const float* gh = g_gh + (long)b * G3H;
    float r  = 1.f / (1.f + __expf(-((gi[j]        + bih[j])        + (gh[j]        + bhh[j]))));
    float zg = 1.f / (1.f + __expf(-((gi[j + 1024] + bih[j + 1024]) + (gh[j + 1024] + bhh[j + 1024]))));
    float ng = tanhf((gi[j + 2048] + bih[j + 2048]) + r * (gh[j + 2048] + bhh[j + 2048]));
    float hp = hprev[(long)b * HH + j];
    float h  = (1.f - zg) * ng + zg * hp;

    g_z[(long)b * KIH + j] = h;
    out_hidden[(long)b * HH + j] = h;
    g_zhi[(long)b * KIH + j] = __float2bfloat16(h);
}

// warp-independent flash attention: each warp owns 16 s-rows, no syncs in main loop
__global__ void __launch_bounds__(256) attn_kernel(const float* __restrict__ enc)
{
    const int b = blockIdx.x >> 3;
    const int c = blockIdx.x & 7;
    const int tid = threadIdx.x;
    const int w = tid >> 5, l = tid & 31;

    __shared__ float sh_h[HH];
    __shared__ float sm_acc[8][HH];
    __shared__ float sm_m[8], sm_l[8];

    *(float4*)(sh_h + tid * 4) = *(const float4*)(g_z + (long)b * KIH + tid * 4);
    __syncthreads();

    float m = -INFINITY, lsum = 0.f;
    float4 acc[8];
    #pragma unroll
    for (int q = 0; q < 8; ++q) acc[q] = make_float4(0.f, 0.f, 0.f, 0.f);

    const int sbase = c * 128 + w * 16;
    for (int i = 0; i < 16; ++i) {
        const int s = sbase + i;
        const float* erow = enc + ((long)s * 64 + b) * 1024;
        float4 ev[8];
        #pragma unroll
        for (int q = 0; q < 8; ++q)
            ev[q] = *(const float4*)(erow + q * 128 + l * 4);
        float p = 0.f;
        #pragma unroll
        for (int q = 0; q < 8; ++q) {
            const float4 hv = *(const float4*)(sh_h + q * 128 + l * 4);
            p += ev[q].x * hv.x + ev[q].y * hv.y + ev[q].z * hv.z + ev[q].w * hv.w;
        }
        p = warpRedSum(p);
        if (l == 0) g_energy[(long)b * SS_ + s] = p;

        float mn = fmaxf(m, p);
        float sc = __expf(m - mn);
        float pe = __expf(p - mn);
        lsum = lsum * sc + pe;
        #pragma unroll
        for (int q = 0; q < 8; ++q) {
            acc[q].x = acc[q].x * sc + pe * ev[q].x;
            acc[q].y = acc[q].y * sc + pe * ev[q].y;
            acc[q].z = acc[q].z * sc + pe * ev[q].z;
            acc[q].w = acc[q].w * sc + pe * ev[q].w;
        }
        m = mn;
    }

    #pragma unroll
    for (int q = 0; q < 8; ++q)
        *(float4*)(&sm_acc[w][q * 128 + l * 4]) = acc[q];
    if (l == 0) { sm_m[w] = m; sm_l[w] = lsum; }
    __syncthreads();

    float M = -INFINITY;
    #pragma unroll
    for (int j = 0; j < 8; ++j) M = fmaxf(M, sm_m[j]);
    float L = 0.f;
    float coef[8];
    #pragma unroll
    for (int j = 0; j < 8; ++j) {
        coef[j] = __expf(sm_m[j] - M);
        L += sm_l[j] * coef[j];
    }

    const int h0 = tid * 4;
    float4 ctx = make_float4(0.f, 0.f, 0.f, 0.f);
    #pragma unroll
    for (int j = 0; j < 8; ++j) {
        float4 pa = *(const float4*)(&sm_acc[j][h0]);
        ctx.x += coef[j] * pa.x;
        ctx.y += coef[j] * pa.y;
        ctx.z += coef[j] * pa.z;
        ctx.w += coef[j] * pa.w;
    }
    *(float4*)(g_pacc + ((long)(b * 8 + c)) * HH + h0) = ctx;
    if (tid == 0) { g_pm[b * 8 + c] = M; g_pl[b * 8 + c] = L; }
}

// merge 8 chunks -> context (fp32 out + bf16 hi into z), attn weights
__global__ void attn_combine(float* __restrict__ out_context,
                             float* __restrict__ out_attn)
{
    int b = blockIdx.x;
    int tid = threadIdx.x;   // 256

    float M = -INFINITY;
    #pragma unroll
    for (int c = 0; c < 8; ++c) M = fmaxf(M, g_pm[b * 8 + c]);
    float L = 0.f;
    float coef[8];
    #pragma unroll
    for (int c = 0; c < 8; ++c) {
        coef[c] = __expf(g_pm[b * 8 + c] - M);
        L += g_pl[b * 8 + c] * coef[c];
    }
    float invL = 1.f / L;

    float4 ctx = make_float4(0.f, 0.f, 0.f, 0.f);
    #pragma unroll
    for (int c = 0; c < 8; ++c) {
        float4 pa = *(const float4*)(g_pacc + ((long)(b * 8 + c)) * HH + tid * 4);
        ctx.x += coef[c] * pa.x;
        ctx.y += coef[c] * pa.y;
        ctx.z += coef[c] * pa.z;
        ctx.w += coef[c] * pa.w;
    }
    ctx.x *= invL; ctx.y *= invL; ctx.z *= invL; ctx.w *= invL;

    *(float4*)(out_context + (long)b * HH + tid * 4) = ctx;
    float cv[4] = {ctx.x, ctx.y, ctx.z, ctx.w};
    #pragma unroll
    for (int q = 0; q < 4; ++q) {
        long idx = (long)b * KIH + 1024 + tid * 4 + q;
        g_zhi[idx] = __float2bfloat16(cv[q]);
    }

    for (int s = tid; s < SS_; s += 256) {
        float w = __expf(g_energy[(long)b * SS_ + s] - M) * invL;
        out_attn[(long)b * SS_ + s] = w;
    }
}

// merge per-tile stats -> lse[b]
__global__ void lsm_merge_kernel()
{
    int b = blockIdx.x;
    int tid = threadIdx.x;   // 128
    __shared__ float sm[4];

    float m = -INFINITY;
    for (int t = tid; t < NTILES; t += 128) m = fmaxf(m, g_tm[t * BB + b]);
    m = warpRedMax(m);
    if ((tid & 31) == 0) sm[tid >> 5] = m;
    __syncthreads();
    float M = fmaxf(fmaxf(sm[0], sm[1]), fmaxf(sm[2], sm[3]));
    __syncthreads();

    float s = 0.f;
    for (int t = tid; t < NTILES; t += 128)
        s += g_tl[t * BB + b] * __expf(g_tm[t * BB + b] - M);
    s = warpRedSum(s);
    if ((tid & 31) == 0) sm[tid >> 5] = s;
    __syncthreads();
    if (tid == 0) {
        float S = sm[0] + sm[1] + sm[2] + sm[3];
        g_lse[b] = M + logf(S);
    }
}

// out[b][v] = biased_logits[b][v] - lse[b]
__global__ void lsm_write_kernel(float* __restrict__ out)
{
    int t = blockIdx.x * blockDim.x + threadIdx.x;   // 512000 threads, 4 elems each
    int idx = t * 4;
    int b = idx / VV;
    float lse = g_lse[b];
    float4 v = *(const float4*)(g_logits + idx);
    v.x -= lse; v.y -= lse; v.z -= lse; v.w -= lse;
    *(float4*)(out + idx) = v;
}

// ---------------- launch ----------------
extern "C" void kernel_launch(void* const* d_in, const int* in_sizes, int n_in,
                              void* d_out, int out_size)
{
    const int*   wi   = (const int*)  d_in[0];
    const float* lctx = (const float*)d_in[1];
    const float* lhid = (const float*)d_in[2];
    const float* enc  = (const float*)d_in[3];
    const float* emb  = (const float*)d_in[4];
    const float* wih  = (const float*)d_in[5];
    const float* whh  = (const float*)d_in[6];
    const float* bih  = (const float*)d_in[7];
    const float* bhh  = (const float*)d_in[8];
    const float* outW = (const float*)d_in[9];
    const float* outb = (const float*)d_in[10];

    float* out        = (float*)d_out;
    float* out_output = out;                         // (B, V)
    float* out_ctx    = out + (long)BB * VV;         // (B, H)
    float* out_hid    = out_ctx + (long)BB * HH;     // (1, B, H)
    float* out_attn   = out_hid + (long)BB * HH;     // (B, 1, S)

    cudaFuncSetAttribute(gates_mma_kernel,  cudaFuncAttributeMaxDynamicSharedMemorySize, SMEM_GEMM);
    cudaFuncSetAttribute(logits_mma_kernel, cudaFuncAttributeMaxDynamicSharedMemorySize, SMEM_LOG);

    prep_kernel      <<<768, 256>>>(wi, lctx, emb, lhid);
    gates_mma_kernel <<<96, 256, SMEM_GEMM>>>(wih, whh);
    gru_kernel       <<<256, 256>>>(bih, bhh, lhid, out_hid);
    attn_kernel      <<<512, 256>>>(enc);
    attn_combine     <<<64, 256>>>(out_ctx, out_attn);
    logits_mma_kernel<<<NTILES, 256, SMEM_LOG>>>(outW, outb);
    lsm_merge_kernel <<<64, 128>>>();
    lsm_write_kernel <<<2000, 256>>>(out_output);
}

// round 16
// speedup vs baseline: 1.0378x; 1.0378x over previous
#include <cuda_runtime.h>
#include <cuda_bf16.h>
#include <math.h>
#include <stdint.h>

// Problem constants
#define BB 64
#define HH 1024
#define SS_ 1024
#define VV 32000
#define KIH 2048   // E + H
#define G3H 3072   // 3*H
#define NTILES 250 // logits tiles of 128 cols

// ---------------- scratch (static device globals) ----------------
__device__ __nv_bfloat16 g_x0hi[BB * KIH];
__device__ __nv_bfloat16 g_x0lo[BB * KIH];
__device__ __nv_bfloat16 g_hhi [BB * HH];
__device__ __nv_bfloat16 g_hlo [BB * HH];
__device__ __nv_bfloat16 g_zhi [BB * KIH];   // [b][ h | ctx ]
__device__ float g_gi[BB * G3H];             // [b][n]
__device__ float g_gh[BB * G3H];             // [b][n]
__device__ float g_z [BB * KIH];             // fp32 h (attn uses [0,1024))
__device__ float g_energy[BB * SS_];
__device__ float g_pm[BB * 8];
__device__ float g_pl[BB * 8];
__device__ float g_pacc[BB * 8 * HH];
__device__ float g_logits[BB * VV];          // biased logits
__device__ float g_tm[NTILES * BB];          // per-tile row max
__device__ float g_tl[NTILES * BB];          // per-tile row sumexp
__device__ float g_lse[BB];

// ---------------- helpers ----------------
__device__ __forceinline__ uint32_t smem_u32(const void* p) {
    uint32_t a;
    asm("{ .reg .u64 t; cvta.to.shared.u64 t, %1; cvt.u32.u64 %0, t; }" : "=r"(a) : "l"(p));
    return a;
}
__device__ __forceinline__ void ldm_x4(uint32_t& r0, uint32_t& r1, uint32_t& r2, uint32_t& r3,
                                       uint32_t addr) {
    asm volatile("ldmatrix.sync.aligned.m8n8.x4.shared.b16 {%0,%1,%2,%3}, [%4];"
        : "=r"(r0), "=r"(r1), "=r"(r2), "=r"(r3) : "r"(addr));
}
__device__ __forceinline__ void mma_bf16(float* c, const uint32_t* a, const uint32_t* b) {
    asm volatile("mma.sync.aligned.m16n8k16.row.col.f32.bf16.bf16.f32 "
        "{%0,%1,%2,%3}, {%4,%5,%6,%7}, {%8,%9}, {%0,%1,%2,%3};"
        : "+f"(c[0]), "+f"(c[1]), "+f"(c[2]), "+f"(c[3])
        : "r"(a[0]), "r"(a[1]), "r"(a[2]), "r"(a[3]), "r"(b[0]), "r"(b[1]));
}
__device__ __forceinline__ uint2 cvt_hi_pair(float4 x) {
    __nv_bfloat162 h0 = __floats2bfloat162_rn(x.x, x.y);
    __nv_bfloat162 h1 = __floats2bfloat162_rn(x.z, x.w);
    uint2 r; r.x = *(uint32_t*)&h0; r.y = *(uint32_t*)&h1;
    return r;
}

__device__ __forceinline__ float warpRedSum(float v) {
    #pragma unroll
    for (int o = 16; o; o >>= 1) v += __shfl_xor_sync(0xffffffffu, v, o);
    return v;
}
__device__ __forceinline__ float warpRedMax(float v) {
    #pragma unroll
    for (int o = 16; o; o >>= 1) v = fmaxf(v, __shfl_xor_sync(0xffffffffu, v, o));
    return v;
}

// ================= gates GEMM (3-product split bf16, unchanged) =================
#define PITCH  72                      // bf16 elements per smem row (144 B)
#define ABYTES (128 * PITCH * 2)       // 18432: 64 hi rows + 64 lo rows
#define WOFF   ABYTES
#define BUFSZ  (2 * ABYTES)            // 36864 per buffer (A + W)
#define SMEM_GEMM (2 * BUFSZ)          // 73728 double-buffered

__device__ __forceinline__ void mma_gemm3(
    const float* __restrict__ W, int K,
    const __nv_bfloat16* __restrict__ Ahi, const __nv_bfloat16* __restrict__ Alo,
    float* __restrict__ OUT, int ldout, int n0)
{
    extern __shared__ char smem[];
    const uint32_t sbase = smem_u32(smem);
    const int tid = threadIdx.x;
    const int w = tid >> 5, l = tid & 31;
    const int wm = w >> 2;
    const int wn = w & 3;
    const int nch = K >> 6;

    const int ar   = tid >> 1;
    const int aseg = (tid & 1) * 32;
    const __nv_bfloat16* asrc =
        (ar < 64 ? Ahi + (long)ar * K : Alo + (long)(ar - 64) * K) + aseg;
    const int adst = (ar * PITCH + aseg) * 2;

    const int wr   = tid >> 2;
    const int wseg = (tid & 3) * 16;
    const float* wsrc = W + (long)(n0 + wr) * K + wseg;
    const int wdst_hi = (wr * PITCH + wseg) * 2;
    const int wdst_lo = ((wr + 64) * PITCH + wseg) * 2;

    float acc[2][2][4];
    #pragma unroll
    for (int i = 0; i < 2; ++i)
        #pragma unroll
        for (int j = 0; j < 2; ++j)
            #pragma unroll
            for (int q = 0; q < 4; ++q) acc[i][j][q] = 0.f;

    uint4  stA[4];
    float4 stW[4];

    #pragma unroll
    for (int i = 0; i < 4; ++i) stA[i] = *(const uint4*)(asrc + i * 8);
    #pragma unroll
    for (int i = 0; i < 4; ++i) stW[i] = *(const float4*)(wsrc + i * 4);
    {
        char* bufA = smem;
        char* bufW = smem + WOFF;
        #pragma unroll
        for (int i = 0; i < 4; ++i) *(uint4*)(bufA + adst + i * 16) = stA[i];
        #pragma unroll
        for (int i = 0; i < 4; ++i) {
            float4 x = stW[i];
            uint2 hp = cvt_hi_pair(x);
            __nv_bfloat162 h0 = *(__nv_bfloat162*)&hp.x;
            __nv_bfloat162 h1 = *(__nv_bfloat162*)&hp.y;
            __nv_bfloat162 l0 = __floats2bfloat162_rn(x.x - __bfloat162float(h0.x),
                                                      x.y - __bfloat162float(h0.y));
            __nv_bfloat162 l1 = __floats2bfloat162_rn(x.z - __bfloat162float(h1.x),
                                                      x.w - __bfloat162float(h1.y));
            uint2 lp; lp.x = *(uint32_t*)&l0; lp.y = *(uint32_t*)&l1;
            *(uint2*)(bufW + wdst_hi + i * 8) = hp;
            *(uint2*)(bufW + wdst_lo + i * 8) = lp;
        }
    }
    __syncthreads();

    for (int c = 0; c < nch; ++c) {
        const int cur = c & 1;
        if (c + 1 < nch) {
            const __nv_bfloat16* as = asrc + (c + 1) * 64;
            #pragma unroll
            for (int i = 0; i < 4; ++i) stA[i] = *(const uint4*)(as + i * 8);
            const float* ws = wsrc + (c + 1) * 64;
            #pragma unroll
            for (int i = 0; i < 4; ++i) stW[i] = *(const float4*)(ws + i * 4);
        }
        const uint32_t sA = sbase + cur * BUFSZ;
        const uint32_t sW = sA + WOFF;

        #pragma unroll
        for (int ks = 0; ks < 4; ++ks) {
            const int k = ks * 16;
            uint32_t ah[2][4], al[2][4], bh[4], bl[4];
            const int rowa = l & 15;
            const int cola = k + (l >> 4) * 8;
            #pragma unroll
            for (int mt = 0; mt < 2; ++mt) {
                const int rhi = wm * 32 + mt * 16 + rowa;
                ldm_x4(ah[mt][0], ah[mt][1], ah[mt][2], ah[mt][3],
                       sA + (rhi * PITCH + cola) * 2);
                ldm_x4(al[mt][0], al[mt][1], al[mt][2], al[mt][3],
                       sA + ((rhi + 64) * PITCH + cola) * 2);
            }
            const int rowb = wn * 16 + ((l >> 4) << 3) + (l & 7);
            const int colb = k + ((l >> 3) & 1) * 8;
            ldm_x4(bh[0], bh[1], bh[2], bh[3], sW + (rowb * PITCH + colb) * 2);
            ldm_x4(bl[0], bl[1], bl[2], bl[3], sW + ((rowb + 64) * PITCH + colb) * 2);

            #pragma unroll
            for (int mt = 0; mt < 2; ++mt)
                #pragma unroll
                for (int nt = 0; nt < 2; ++nt) {
                    mma_bf16(acc[mt][nt], ah[mt], &bh[nt * 2]);
                    mma_bf16(acc[mt][nt], ah[mt], &bl[nt * 2]);
                    mma_bf16(acc[mt][nt], al[mt], &bh[nt * 2]);
                }
        }

        if (c + 1 < nch) {
            char* bufA = smem + (cur ^ 1) * BUFSZ;
            char* bufW = bufA + WOFF;
            #pragma unroll
            for (int i = 0; i < 4; ++i) *(uint4*)(bufA + adst + i * 16) = stA[i];
            #pragma unroll
            for (int i = 0; i < 4; ++i) {
                float4 x = stW[i];
                uint2 hp = cvt_hi_pair(x);
                __nv_bfloat162 h0 = *(__nv_bfloat162*)&hp.x;
                __nv_bfloat162 h1 = *(__nv_bfloat162*)&hp.y;
                __nv_bfloat162 l0 = __floats2bfloat162_rn(x.x - __bfloat162float(h0.x),
                                                          x.y - __bfloat162float(h0.y));
                __nv_bfloat162 l1 = __floats2bfloat162_rn(x.z - __bfloat162float(h1.x),
                                                          x.w - __bfloat162float(h1.y));
                uint2 lp; lp.x = *(uint32_t*)&l0; lp.y = *(uint32_t*)&l1;
                *(uint2*)(bufW + wdst_hi + i * 8) = hp;
                *(uint2*)(bufW + wdst_lo + i * 8) = lp;
            }
        }
        __syncthreads();
    }

    #pragma unroll
    for (int mt = 0; mt < 2; ++mt) {
        #pragma unroll
        for (int nt = 0; nt < 2; ++nt) {
            const int row = wm * 32 + mt * 16 + (l >> 2);
            const int col = n0 + wn * 16 + nt * 8 + (l & 3) * 2;
            *(float2*)(OUT + (long)row * ldout + col)       = make_float2(acc[mt][nt][0], acc[mt][nt][1]);
            *(float2*)(OUT + (long)(row + 8) * ldout + col) = make_float2(acc[mt][nt][2], acc[mt][nt][3]);
        }
    }
}

__global__ void __launch_bounds__(256, 2) gates_mma_kernel(
    const float* __restrict__ wih, const float* __restrict__ whh)
{
    if (blockIdx.x < 48)
        mma_gemm3(wih, KIH, g_x0hi, g_x0lo, g_gi, G3H, blockIdx.x * 64);
    else
        mma_gemm3(whh, HH, g_hhi, g_hlo, g_gh, G3H, (blockIdx.x - 48) * 64);
}

// ================= logits GEMM: disjoint W coverage, W prefetch depth 4 =================
// smem: A double buffer only: 2 x 64 rows x PITCH bf16
#define LA_BYTES (64 * PITCH * 2)     // 9216 per buffer
#define SMEM_LOG (2 * LA_BYTES)       // 18432

__global__ void __launch_bounds__(256, 2) logits_mma_kernel(const float* __restrict__ outW,
                                                            const float* __restrict__ outb)
{
    extern __shared__ char smem[];
    const uint32_t sbase = smem_u32(smem);
    const int tid = threadIdx.x;
    const int w = tid >> 5, l = tid & 31;
    const int tile = blockIdx.x;
    const int n0 = tile * 128;

    // A staging: row = tid>>2 (0..63), 16 bf16 per thread per chunk
    const int ar   = tid >> 2;
    const int aseg = (tid & 3) * 16;
    const __nv_bfloat16* asrc = g_zhi + (long)ar * KIH + aseg;
    const int adst = (ar * PITCH + aseg) * 2;

    // W direct pointers: warp w covers n-rows [n0+16w, n0+16w+16) -- disjoint across warps
    const float* wp0 = outW + (long)(n0 + w * 16 + 0 + (l >> 2)) * KIH + (l & 3) * 2;
    const float* wp1 = outW + (long)(n0 + w * 16 + 8 + (l >> 2)) * KIH + (l & 3) * 2;

    float acc[4][2][4];
    #pragma unroll
    for (int i = 0; i < 4; ++i)
        #pragma unroll
        for (int j = 0; j < 2; ++j)
            #pragma unroll
            for (int q = 0; q < 4; ++q) acc[i][j][q] = 0.f;

    // prologue: stage A chunk 0; load W steps 0..3 (depth-4 register pipeline)
    {
        char* buf = smem;
        *(uint4*)(buf + adst)      = *(const uint4*)(asrc);
        *(uint4*)(buf + adst + 16) = *(const uint4*)(asrc + 8);
    }
    float2 wf[4][4];
    #pragma unroll
    for (int s = 0; s < 4; ++s) {
        const int kn = s * 16;
        wf[s][0] = *(const float2*)(wp0 + kn);  wf[s][1] = *(const float2*)(wp0 + kn + 8);
        wf[s][2] = *(const float2*)(wp1 + kn);  wf[s][3] = *(const float2*)(wp1 + kn + 8);
    }
    __syncthreads();

    for (int c = 0; c < 32; ++c) {
        const uint32_t sA = sbase + (c & 1) * LA_BYTES;
        uint4 an0, an1;
        if (c + 1 < 32) {
            an0 = *(const uint4*)(asrc + (c + 1) * 64);
            an1 = *(const uint4*)(asrc + (c + 1) * 64 + 8);
        }
        #pragma unroll
        for (int ks = 0; ks < 4; ++ks) {
            const int kk = c * 4 + ks;
            const int slot = kk & 3;
            // convert current W step to bf16 fragments
            uint32_t breg[4];
            #pragma unroll
            for (int i = 0; i < 4; ++i) {
                __nv_bfloat162 bb = __floats2bfloat162_rn(wf[slot][i].x, wf[slot][i].y);
                breg[i] = *(uint32_t*)&bb;
            }
            // refill this slot with step kk+4 (pipeline depth 4)
            if (kk + 4 < 128) {
                const int kn = (kk + 4) * 16;
                wf[slot][0] = *(const float2*)(wp0 + kn);  wf[slot][1] = *(const float2*)(wp0 + kn + 8);
                wf[slot][2] = *(const float2*)(wp1 + kn);  wf[slot][3] = *(const float2*)(wp1 + kn + 8);
            }
            // A frags from smem: all 4 m-tiles
            const int rowa = l & 15;
            const int cola = ks * 16 + (l >> 4) * 8;
            uint32_t ah[4][4];
            #pragma unroll
            for (int mt = 0; mt < 4; ++mt) {
                ldm_x4(ah[mt][0], ah[mt][1], ah[mt][2], ah[mt][3],
                       sA + ((mt * 16 + rowa) * PITCH + cola) * 2);
            }
            // 8 MMAs
            #pragma unroll
            for (int mt = 0; mt < 4; ++mt) {
                mma_bf16(acc[mt][0], ah[mt], &breg[0]);
                mma_bf16(acc[mt][1], ah[mt], &breg[2]);
            }
        }
        if (c + 1 < 32) {
            char* buf = smem + ((c + 1) & 1) * LA_BYTES;
            *(uint4*)(buf + adst)      = an0;
            *(uint4*)(buf + adst + 16) = an1;
        }
        __syncthreads();
    }

    // bias add
    #pragma unroll
    for (int nt = 0; nt < 2; ++nt) {
        const int col = n0 + w * 16 + nt * 8 + (l & 3) * 2;
        float2 bb = *(const float2*)(outb + col);
        #pragma unroll
        for (int mt = 0; mt < 4; ++mt) {
            acc[mt][nt][0] += bb.x; acc[mt][nt][1] += bb.y;
            acc[mt][nt][2] += bb.x; acc[mt][nt][3] += bb.y;
        }
    }

    // store biased logits
    #pragma unroll
    for (int mt = 0; mt < 4; ++mt) {
        #pragma unroll
        for (int nt = 0; nt < 2; ++nt) {
            const int row = mt * 16 + (l >> 2);
            const int col = n0 + w * 16 + nt * 8 + (l & 3) * 2;
            *(float2*)(g_logits + (long)row * VV + col)       = make_float2(acc[mt][nt][0], acc[mt][nt][1]);
            *(float2*)(g_logits + (long)(row + 8) * VV + col) = make_float2(acc[mt][nt][2], acc[mt][nt][3]);
        }
    }

    // per-row tile stats (max + sumexp over 128 cols; 8 warp-columns of 16)
    {
        float* sm_em = (float*)smem;         // [8][64]
        float* sm_el = sm_em + 512;          // [8][64]
        float rmax[8], rsum[8];
        #pragma unroll
        for (int r = 0; r < 8; ++r) {
            const int mt = r >> 1, hf = r & 1;
            float v = fmaxf(fmaxf(acc[mt][0][hf * 2], acc[mt][0][hf * 2 + 1]),
                            fmaxf(acc[mt][1][hf * 2], acc[mt][1][hf * 2 + 1]));
            v = fmaxf(v, __shfl_xor_sync(0xffffffffu, v, 1));
            v = fmaxf(v, __shfl_xor_sync(0xffffffffu, v, 2));
            rmax[r] = v;
        }
        __syncthreads();
        if ((l & 3) == 0) {
            #pragma unroll
            for (int r = 0; r < 8; ++r) {
                const int mt = r >> 1, hf = r & 1;
                const int row = mt * 16 + hf * 8 + (l >> 2);
                sm_em[w * 64 + row] = rmax[r];
            }
        }
        __syncthreads();
        #pragma unroll
        for (int r = 0; r < 8; ++r) {
            const int mt = r >> 1, hf = r & 1;
            const int row = mt * 16 + hf * 8 + (l >> 2);
            float gm = -INFINITY;
            #pragma unroll
            for (int j = 0; j < 8; ++j) gm = fmaxf(gm, sm_em[j * 64 + row]);
            rmax[r] = gm;
            float s = __expf(acc[mt][0][hf * 2]     - gm) + __expf(acc[mt][0][hf * 2 + 1] - gm)
                    + __expf(acc[mt][1][hf * 2]     - gm) + __expf(acc[mt][1][hf * 2 + 1] - gm);
            s += __shfl_xor_sync(0xffffffffu, s, 1);
            s += __shfl_xor_sync(0xffffffffu, s, 2);
            rsum[r] = s;
        }
        __syncthreads();
        if ((l & 3) == 0) {
            #pragma unroll
            for (int r = 0; r < 8; ++r) {
                const int mt = r >> 1, hf = r & 1;
                const int row = mt * 16 + hf * 8 + (l >> 2);
                sm_el[w * 64 + row] = rsum[r];
            }
        }
        __syncthreads();
        if (w == 0 && (l & 3) == 0) {
            #pragma unroll
            for (int r = 0; r < 8; ++r) {
                const int mt = r >> 1, hf = r & 1;
                const int row = mt * 16 + hf * 8 + (l >> 2);
                float tot = 0.f;
                #pragma unroll
                for (int j = 0; j < 8; ++j) tot += sm_el[j * 64 + row];
                g_tm[tile * BB + row] = rmax[r];
                g_tl[tile * BB + row] = tot;
            }
        }
    }
}

// ---------------- kernels ----------------

// split x0 = [emb|lctx] and hprev into bf16 hi/lo
__global__ void prep_kernel(const int* __restrict__ wi,
                            const float* __restrict__ lctx,
                            const float* __restrict__ emb,
                            const float* __restrict__ lhid)
{
    int t = blockIdx.x * blockDim.x + threadIdx.x;   // 196608
    if (t < BB * KIH) {
        int b = t >> 11, k = t & 2047;
        float x = (k < 1024) ? emb[(long)wi[b] * 1024 + k] : lctx[(long)b * HH + (k - 1024)];
        __nv_bfloat16 h = __float2bfloat16(x);
        g_x0hi[t] = h;
        g_x0lo[t] = __float2bfloat16(x - __bfloat162float(h));
    } else {
        int t2 = t - BB * KIH;
        float x = lhid[t2];
        __nv_bfloat16 h = __float2bfloat16(x);
        g_hhi[t2] = h;
        g_hlo[t2] = __float2bfloat16(x - __bfloat162float(h));
    }
}

// GRU gate nonlinearity -> h (fp32 + bf16 hi for logits A)
__global__ void gru_kernel(const float* __restrict__ bih,
                           const float* __restrict__ bhh,
                           const float* __restrict__ hprev,
                           float* __restrict__ out_hidden)
{
    int t = blockIdx.x * blockDim.x + threadIdx.x;   // 65536
    int b = t >> 10;
    int j = t & 1023;
    const float* gi = g_gi + (long)b * G3H;
    const float* gh = g_gh + (long)b * G3H;
    float r  = 1.f / (1.f + __expf(-((gi[j]        + bih[j])        + (gh[j]        + bhh[j]))));
    float zg = 1.f / (1.f + __expf(-((gi[j + 1024] + bih[j + 1024]) + (gh[j + 1024] + bhh[j + 1024]))));
    float ng = tanhf((gi[j + 2048] + bih[j + 2048]) + r * (gh[j + 2048] + bhh[j + 2048]));
    float hp = hprev[(long)b * HH + j];
    float h  = (1.f - zg) * ng + zg * hp;

    g_z[(long)b * KIH + j] = h;
    out_hidden[(long)b * HH + j] = h;
    g_zhi[(long)b * KIH + j] = __float2bfloat16(h);
}

// warp-independent flash attention: each warp owns 16 s-rows, no syncs in main loop
__global__ void __launch_bounds__(256) attn_kernel(const float* __restrict__ enc)
{
    const int b = blockIdx.x >> 3;
    const int c = blockIdx.x & 7;
    const int tid = threadIdx.x;
    const int w = tid >> 5, l = tid & 31;

    __shared__ float sh_h[HH];
    __shared__ float sm_acc[8][HH];
    __shared__ float sm_m[8], sm_l[8];

    *(float4*)(sh_h + tid * 4) = *(const float4*)(g_z + (long)b * KIH + tid * 4);
    __syncthreads();

    float m = -INFINITY, lsum = 0.f;
    float4 acc[8];
    #pragma unroll
    for (int q = 0; q < 8; ++q) acc[q] = make_float4(0.f, 0.f, 0.f, 0.f);

    const int sbase = c * 128 + w * 16;
    for (int i = 0; i < 16; ++i) {
        const int s = sbase + i;
        const float* erow = enc + ((long)s * 64 + b) * 1024;
        float4 ev[8];
        #pragma unroll
        for (int q = 0; q < 8; ++q)
            ev[q] = *(const float4*)(erow + q * 128 + l * 4);
        float p = 0.f;
        #pragma unroll
        for (int q = 0; q < 8; ++q) {
            const float4 hv = *(const float4*)(sh_h + q * 128 + l * 4);
            p += ev[q].x * hv.x + ev[q].y * hv.y + ev[q].z * hv.z + ev[q].w * hv.w;
        }
        p = warpRedSum(p);
        if (l == 0) g_energy[(long)b * SS_ + s] = p;

        float mn = fmaxf(m, p);
        float sc = __expf(m - mn);
        float pe = __expf(p - mn);
        lsum = lsum * sc + pe;
        #pragma unroll
        for (int q = 0; q < 8; ++q) {
            acc[q].x = acc[q].x * sc + pe * ev[q].x;
            acc[q].y = acc[q].y * sc + pe * ev[q].y;
            acc[q].z = acc[q].z * sc + pe * ev[q].z;
            acc[q].w = acc[q].w * sc + pe * ev[q].w;
        }
        m = mn;
    }

    #pragma unroll
    for (int q = 0; q < 8; ++q)
        *(float4*)(&sm_acc[w][q * 128 + l * 4]) = acc[q];
    if (l == 0) { sm_m[w] = m; sm_l[w] = lsum; }
    __syncthreads();

    float M = -INFINITY;
    #pragma unroll
    for (int j = 0; j < 8; ++j) M = fmaxf(M, sm_m[j]);
    float L = 0.f;
    float coef[8];
    #pragma unroll
    for (int j = 0; j < 8; ++j) {
        coef[j] = __expf(sm_m[j] - M);
        L += sm_l[j] * coef[j];
    }

    const int h0 = tid * 4;
    float4 ctx = make_float4(0.f, 0.f, 0.f, 0.f);
    #pragma unroll
    for (int j = 0; j < 8; ++j) {
        float4 pa = *(const float4*)(&sm_acc[j][h0]);
        ctx.x += coef[j] * pa.x;
        ctx.y += coef[j] * pa.y;
        ctx.z += coef[j] * pa.z;
        ctx.w += coef[j] * pa.w;
    }
    *(float4*)(g_pacc + ((long)(b * 8 + c)) * HH + h0) = ctx;
    if (tid == 0) { g_pm[b * 8 + c] = M; g_pl[b * 8 + c] = L; }
}

// merge 8 chunks -> context (fp32 out + bf16 hi into z), attn weights
__global__ void attn_combine(float* __restrict__ out_context,
                             float* __restrict__ out_attn)
{
    int b = blockIdx.x;
    int tid = threadIdx.x;   // 256

    float M = -INFINITY;
    #pragma unroll
    for (int c = 0; c < 8; ++c) M = fmaxf(M, g_pm[b * 8 + c]);
    float L = 0.f;
    float coef[8];
    #pragma unroll
    for (int c = 0; c < 8; ++c) {
        coef[c] = __expf(g_pm[b * 8 + c] - M);
        L += g_pl[b * 8 + c] * coef[c];
    }
    float invL = 1.f / L;

    float4 ctx = make_float4(0.f, 0.f, 0.f, 0.f);
    #pragma unroll
    for (int c = 0; c < 8; ++c) {
        float4 pa = *(const float4*)(g_pacc + ((long)(b * 8 + c)) * HH + tid * 4);
        ctx.x += coef[c] * pa.x;
        ctx.y += coef[c] * pa.y;
        ctx.z += coef[c] * pa.z;
        ctx.w += coef[c] * pa.w;
    }
    ctx.x *= invL; ctx.y *= invL; ctx.z *= invL; ctx.w *= invL;

    *(float4*)(out_context + (long)b * HH + tid * 4) = ctx;
    float cv[4] = {ctx.x, ctx.y, ctx.z, ctx.w};
    #pragma unroll
    for (int q = 0; q < 4; ++q) {
        long idx = (long)b * KIH + 1024 + tid * 4 + q;
        g_zhi[idx] = __float2bfloat16(cv[q]);
    }

    for (int s = tid; s < SS_; s += 256) {
        float w = __expf(g_energy[(long)b * SS_ + s] - M) * invL;
        out_attn[(long)b * SS_ + s] = w;
    }
}

// merge per-tile stats -> lse[b]
__global__ void lsm_merge_kernel()
{
    int b = blockIdx.x;
    int tid = threadIdx.x;   // 128
    __shared__ float sm[4];

    float m = -INFINITY;
    for (int t = tid; t < NTILES; t += 128) m = fmaxf(m, g_tm[t * BB + b]);
    m = warpRedMax(m);
    if ((tid & 31) == 0) sm[tid >> 5] = m;
    __syncthreads();
    float M = fmaxf(fmaxf(sm[0], sm[1]), fmaxf(sm[2], sm[3]));
    __syncthreads();

    float s = 0.f;
    for (int t = tid; t < NTILES; t += 128)
        s += g_tl[t * BB + b] * __expf(g_tm[t * BB + b] - M);
    s = warpRedSum(s);
    if ((tid & 31) == 0) sm[tid >> 5] = s;
    __syncthreads();
    if (tid == 0) {
        float S = sm[0] + sm[1] + sm[2] + sm[3];
        g_lse[b] = M + logf(S);
    }
}

// out[b][v] = biased_logits[b][v] - lse[b]
__global__ void lsm_write_kernel(float* __restrict__ out)
{
    int t = blockIdx.x * blockDim.x + threadIdx.x;   // 512000 threads, 4 elems each
    int idx = t * 4;
    int b = idx / VV;
    float lse = g_lse[b];
    float4 v = *(const float4*)(g_logits + idx);
    v.x -= lse; v.y -= lse; v.z -= lse; v.w -= lse;
    *(float4*)(out + idx) = v;
}

// ---------------- launch ----------------
extern "C" void kernel_launch(void* const* d_in, const int* in_sizes, int n_in,
                              void* d_out, int out_size)
{
    const int*   wi   = (const int*)  d_in[0];
    const float* lctx = (const float*)d_in[1];
    const float* lhid = (const float*)d_in[2];
    const float* enc  = (const float*)d_in[3];
    const float* emb  = (const float*)d_in[4];
    const float* wih  = (const float*)d_in[5];
    const float* whh  = (const float*)d_in[6];
    const float* bih  = (const float*)d_in[7];
    const float* bhh  = (const float*)d_in[8];
    const float* outW = (const float*)d_in[9];
    const float* outb = (const float*)d_in[10];

    float* out        = (float*)d_out;
    float* out_output = out;                         // (B, V)
    float* out_ctx    = out + (long)BB * VV;         // (B, H)
    float* out_hid    = out_ctx + (long)BB * HH;     // (1, B, H)
    float* out_attn   = out_hid + (long)BB * HH;     // (B, 1, S)

    cudaFuncSetAttribute(gates_mma_kernel,  cudaFuncAttributeMaxDynamicSharedMemorySize, SMEM_GEMM);
    cudaFuncSetAttribute(logits_mma_kernel, cudaFuncAttributeMaxDynamicSharedMemorySize, SMEM_LOG);

    prep_kernel      <<<768, 256>>>(wi, lctx, emb, lhid);
    gates_mma_kernel <<<96, 256, SMEM_GEMM>>>(wih, whh);
    gru_kernel       <<<256, 256>>>(bih, bhh, lhid, out_hid);
    attn_kernel      <<<512, 256>>>(enc);
    attn_combine     <<<64, 256>>>(out_ctx, out_attn);
    logits_mma_kernel<<<NTILES, 256, SMEM_LOG>>>(outW, outb);
    lsm_merge_kernel <<<64, 128>>>();
    lsm_write_kernel <<<2000, 256>>>(out_output);
}